// round 5
// baseline (speedup 1.0000x reference)
#include <cuda_runtime.h>
#include <cstdint>

// Problem constants (fixed by the reference)
#define Bp    4
#define Tp    512
#define Kp    256
#define DENC  256
#define DKp   256
#define UN    128
#define TT    8     // timesteps per block
#define UC    16    // u-rows per kk smem chunk
#define NCHUNK (UN / UC)   // 8
#define NTHR  512   // 16 warps

// Scratch: kkT[b][u][k] = (knowledge[b] @ W2 + b2) transposed to [U][K]
__device__ float g_kkT[Bp * UN * Kp];   // 512 KB (L2 resident)

static __device__ __forceinline__ uint32_t smem_u32(const void* p) {
    return (uint32_t)__cvta_generic_to_shared(p);
}
static __device__ __forceinline__ void cp_async16(uint32_t dst, const void* src) {
    asm volatile("cp.async.cg.shared.global [%0], [%1], 16;\n" :: "r"(dst), "l"(src));
}
static __device__ __forceinline__ void cp_commit() {
    asm volatile("cp.async.commit_group;\n");
}
template <int N>
static __device__ __forceinline__ void cp_wait() {
    asm volatile("cp.async.wait_group %0;\n" :: "n"(N));
}

// ---------------------------------------------------------------------------
// Pre-kernel: kkT[b][u][k] = sum_d knowledge[b,k,d] * W2[d,u] + b2[u]
// grid = B * (K/8) = 128 blocks, 256 threads.
// ---------------------------------------------------------------------------
__global__ void __launch_bounds__(256) kk_pre_kernel(
    const float* __restrict__ kn,
    const float* __restrict__ W2,
    const float* __restrict__ b2)
{
    const int b  = blockIdx.x >> 5;          // 0..3
    const int k0 = (blockIdx.x & 31) * 8;    // 0..248

    __shared__ float knS[8][DKp];            // 8 KB
    const int tid = threadIdx.x;
    for (int i = tid; i < 8 * DKp; i += 256)
        knS[i >> 8][i & 255] = kn[(b * Kp + k0) * DKp + i];
    __syncthreads();

    const int u    = tid & 127;
    const int half = tid >> 7;               // rows half*4 .. half*4+3
    const float bb = b2[u];
    float a0 = bb, a1 = bb, a2 = bb, a3 = bb;
    #pragma unroll 8
    for (int d = 0; d < DKp; d++) {
        const float w = W2[d * UN + u];      // coalesced across threads
        a0 = fmaf(knS[half * 4 + 0][d], w, a0);
        a1 = fmaf(knS[half * 4 + 1][d], w, a1);
        a2 = fmaf(knS[half * 4 + 2][d], w, a2);
        a3 = fmaf(knS[half * 4 + 3][d], w, a3);
    }
    float4* dst = (float4*)(g_kkT + (size_t)b * UN * Kp + (size_t)u * Kp + k0 + half * 4);
    *dst = make_float4(a0, a1, a2, a3);
}

// ---------------------------------------------------------------------------
// Main fused kernel, 512 threads (16 warps):
//   phase A splits each timestep's K across a pair of warps for 2x latency
//   hiding at the same grid size.
// grid = B * (T/TT) = 256 blocks.
// ---------------------------------------------------------------------------
__global__ void __launch_bounds__(NTHR) attn_main_kernel(
    const float* __restrict__ kn,
    const float* __restrict__ enc,
    const float* __restrict__ W1,
    const float* __restrict__ b1,
    const float* __restrict__ V,
    float* __restrict__ out)
{
    // encS dead after phase 0; wT born after phase A -> alias them.
    __shared__ union {
        float encS[TT][DENC];                // 8 KB
        float wT[Kp][TT];                    // 8 KB (weights, transposed)
    } uS;
    __shared__ float eS[TT][UN];             // 4 KB
    __shared__ float Vs[UN];                 // 0.5 KB
    __shared__ __align__(16) float kkS[2][UC][Kp];  // 32 KB double buffer
    __shared__ float redMax[16], redSum[16];

    const int tid = threadIdx.x;
    const int b   = blockIdx.x >> 6;                 // 0..3
    const int t0  = (blockIdx.x & 63) * TT;          // 0..504

    const float* kkb = g_kkT + (size_t)b * UN * Kp;

    // ---- Prefetch kk chunk 0 (overlaps with phase 0 compute) ----
    {
        const float4* src = (const float4*)kkb;      // chunk 0 base: 1024 float4
        #pragma unroll
        for (int r = 0; r < 2; r++) {
            const int i = r * NTHR + tid;
            cp_async16(smem_u32(&kkS[0][0][0]) + i * 16, src + i);
        }
        cp_commit();
    }

    // Stage encoder rows (512 float4) + V
    {
        const float4* esrc = (const float4*)(enc + (size_t)(b * Tp + t0) * DENC);
        ((float4*)&uS.encS[0][0])[tid] = esrc[tid];
        if (tid < UN) Vs[tid] = V[tid];
    }
    __syncthreads();

    // ---- Phase 0: e[tt][u] = enc_row @ W1 + b1 (2 rows per thread) ----
    {
        const int u = tid & 127;
        const int q = tid >> 7;                      // 0..3 -> rows q*2, q*2+1
        const float bb = b1[u];
        float a0 = bb, a1 = bb;
        #pragma unroll 8
        for (int d = 0; d < DENC; d++) {
            const float w = W1[d * UN + u];          // coalesced, L2 resident
            a0 = fmaf(uS.encS[q * 2 + 0][d], w, a0);
            a1 = fmaf(uS.encS[q * 2 + 1][d], w, a1);
        }
        eS[q * 2 + 0][u] = a0;
        eS[q * 2 + 1][u] = a1;
    }
    __syncthreads();   // encS now dead; wT may be written after this point

    // ---- Phase A: scores. warp = (tt, k-half); lane owns k = kh*128+lane+32j ----
    const int warp = tid >> 5;
    const int lane = tid & 31;
    const int tt   = warp >> 1;                      // 0..7
    const int kh   = warp & 1;                       // 0..1

    float s[4];
    #pragma unroll
    for (int j = 0; j < 4; j++) s[j] = 0.f;

    for (int c = 0; c < NCHUNK; c++) {
        if (c + 1 < NCHUNK) {
            const float4* src = (const float4*)(kkb + (size_t)(c + 1) * UC * Kp);
            uint32_t dstb = smem_u32(&kkS[(c + 1) & 1][0][0]);
            #pragma unroll
            for (int r = 0; r < 2; r++) {
                const int i = r * NTHR + tid;
                cp_async16(dstb + i * 16, src + i);
            }
            cp_commit();
            cp_wait<1>();   // current chunk's group complete
        } else {
            cp_wait<0>();
        }
        __syncthreads();    // tile visible to all warps

        const float* tile = &kkS[c & 1][0][0] + kh * 128 + lane;
        const int ub = c * UC;
        #pragma unroll 4
        for (int u = 0; u < UC; u++) {
            const float e = eS[tt][ub + u];          // smem broadcast
            const float v = Vs[ub + u];              // smem broadcast
            const float* row = tile + u * Kp;        // LDS, conflict-free
            #pragma unroll
            for (int j = 0; j < 4; j++) {
                float th;
                const float x = e + row[j * 32];
                asm("tanh.approx.f32 %0, %1;" : "=f"(th) : "f"(x));
                s[j] = fmaf(th, v, s[j]);
            }
        }
        __syncthreads();    // all warps done with this buffer before overwrite
    }

    // ---- Softmax over K=256 split across the warp pair (tt, 0/1) ----
    float mx = fmaxf(fmaxf(s[0], s[1]), fmaxf(s[2], s[3]));
    #pragma unroll
    for (int o = 16; o > 0; o >>= 1) mx = fmaxf(mx, __shfl_xor_sync(0xffffffffu, mx, o));
    if (lane == 0) redMax[warp] = mx;
    __syncthreads();
    mx = fmaxf(redMax[warp], redMax[warp ^ 1]);

    float sum = 0.f;
    #pragma unroll
    for (int j = 0; j < 4; j++) { s[j] = __expf(s[j] - mx); sum += s[j]; }
    #pragma unroll
    for (int o = 16; o > 0; o >>= 1) sum += __shfl_xor_sync(0xffffffffu, sum, o);
    if (lane == 0) redSum[warp] = sum;
    __syncthreads();
    const float inv = 1.0f / (redSum[warp] + redSum[warp ^ 1]);
    #pragma unroll
    for (int j = 0; j < 4; j++)
        uS.wT[kh * 128 + j * 32 + lane][tt] = s[j] * inv;   // transposed for phase C
    __syncthreads();

    // ---- Phase C: context. half g owns timesteps g*4..g*4+3, full K ----
    const int d = tid & 255;                         // 0..255 == DKp
    const int g = tid >> 8;                          // 0..1
    float acc[4];
    #pragma unroll
    for (int r = 0; r < 4; r++) acc[r] = 0.f;

    const float* knb = kn + (size_t)b * Kp * DKp + d;
    #pragma unroll 4
    for (int k = 0; k < Kp; k++) {
        const float kv = knb[(size_t)k * DKp];       // coalesced, L1/L2 resident
        const float4 w = *(const float4*)&uS.wT[k][g * 4]; // broadcast
        acc[0] = fmaf(w.x, kv, acc[0]);
        acc[1] = fmaf(w.y, kv, acc[1]);
        acc[2] = fmaf(w.z, kv, acc[2]);
        acc[3] = fmaf(w.w, kv, acc[3]);
    }
    #pragma unroll
    for (int r = 0; r < 4; r++)
        out[((size_t)(b * Tp + t0 + g * 4 + r)) * DKp + d] = acc[r];
}

// ---------------------------------------------------------------------------
// Harness entry point
// ---------------------------------------------------------------------------
extern "C" void kernel_launch(void* const* d_in, const int* in_sizes, int n_in,
                              void* d_out, int out_size)
{
    const float* kn  = (const float*)d_in[0];  // knowledge_onehot [B,K,D_K]
    const float* enc = (const float*)d_in[1];  // encoder_outputs  [B,T,D_ENC]
    const float* W1  = (const float*)d_in[2];  // [D_ENC,U]
    const float* b1  = (const float*)d_in[3];  // [U]
    const float* W2  = (const float*)d_in[4];  // [D_K,U]
    const float* b2  = (const float*)d_in[5];  // [U]
    const float* V   = (const float*)d_in[6];  // [U,1]
    // d_in[7] = bV: constant shift on scores, softmax-invariant -> ignored.
    float* out = (float*)d_out;                // context [B,T,D_K] fp32

    kk_pre_kernel<<<Bp * (Kp / 8), 256>>>(kn, W2, b2);
    attn_main_kernel<<<Bp * (Tp / TT), NTHR>>>(kn, enc, W1, b1, V, out);
}

// round 6
// speedup vs baseline: 1.0483x; 1.0483x over previous
#include <cuda_runtime.h>
#include <cstdint>

// Problem constants (fixed by the reference)
#define Bp    4
#define Tp    512
#define Kp    256
#define DENC  256
#define DKp   256
#define UN    128
#define TT    8     // timesteps per block
#define NTHR  512   // 16 warps: warp = (tt, u-half)

// Scratch: kkT[b][u][k] = (knowledge[b] @ W2 + b2) transposed to [U][K]
__device__ float g_kkT[Bp * UN * Kp];   // 512 KB (L2/L1 resident)

// ---------------------------------------------------------------------------
// Pre-kernel: kkT[b][u][k] = sum_d knowledge[b,k,d] * W2[d,u] + b2[u]
// grid = B * (K/8) = 128 blocks, 256 threads.
// ---------------------------------------------------------------------------
__global__ void __launch_bounds__(256) kk_pre_kernel(
    const float* __restrict__ kn,
    const float* __restrict__ W2,
    const float* __restrict__ b2)
{
    const int b  = blockIdx.x >> 5;          // 0..3
    const int k0 = (blockIdx.x & 31) * 8;    // 0..248

    __shared__ float knS[8][DKp];            // 8 KB
    const int tid = threadIdx.x;
    for (int i = tid; i < 8 * DKp; i += 256)
        knS[i >> 8][i & 255] = kn[(b * Kp + k0) * DKp + i];
    __syncthreads();

    const int u    = tid & 127;
    const int half = tid >> 7;               // rows half*4 .. half*4+3
    const float bb = b2[u];
    float a0 = bb, a1 = bb, a2 = bb, a3 = bb;
    #pragma unroll 8
    for (int d = 0; d < DKp; d++) {
        const float w = W2[d * UN + u];      // coalesced across threads
        a0 = fmaf(knS[half * 4 + 0][d], w, a0);
        a1 = fmaf(knS[half * 4 + 1][d], w, a1);
        a2 = fmaf(knS[half * 4 + 2][d], w, a2);
        a3 = fmaf(knS[half * 4 + 3][d], w, a3);
    }
    float4* dst = (float4*)(g_kkT + (size_t)b * UN * Kp + (size_t)u * Kp + k0 + half * 4);
    *dst = make_float4(a0, a1, a2, a3);
}

// ---------------------------------------------------------------------------
// Main fused kernel, 512 threads (16 warps), barrier-free score loop:
//   warp = (tt, uh). Each warp streams its private 64 kkT rows from
//   global (L1-hot), accumulating partial scores for the FULL K=256.
//   Partials combine in smem, pair softmax, then context GEMV.
// grid = B * (T/TT) = 256 blocks.
// ---------------------------------------------------------------------------
__global__ void __launch_bounds__(NTHR, 2) attn_main_kernel(
    const float* __restrict__ kn,
    const float* __restrict__ enc,
    const float* __restrict__ W1,
    const float* __restrict__ b1,
    const float* __restrict__ V,
    float* __restrict__ out)
{
    // encS dead after phase 0; wT (tt-major!) born at softmax -> alias.
    __shared__ union {
        float encS[TT][DENC];                // 8 KB
        float wT[TT][Kp];                    // 8 KB
    } uS;
    __shared__ float eS[TT][UN];             // 4 KB
    __shared__ float Vs[UN];                 // 0.5 KB
    __shared__ __align__(16) float sP[2][TT][Kp];   // 16 KB partial scores
    __shared__ float redMax[16], redSum[16];

    const int tid = threadIdx.x;
    const int b   = blockIdx.x >> 6;                 // 0..3
    const int t0  = (blockIdx.x & 63) * TT;          // 0..504

    // Stage encoder rows (512 float4) + V
    {
        const float4* esrc = (const float4*)(enc + (size_t)(b * Tp + t0) * DENC);
        ((float4*)&uS.encS[0][0])[tid] = esrc[tid];
        if (tid < UN) Vs[tid] = V[tid];
    }
    __syncthreads();

    // ---- Phase 0: e[tt][u] = enc_row @ W1 + b1 (2 rows per thread) ----
    {
        const int u = tid & 127;
        const int q = tid >> 7;                      // 0..3 -> rows q*2, q*2+1
        const float bb = b1[u];
        float a0 = bb, a1 = bb;
        #pragma unroll 8
        for (int d = 0; d < DENC; d++) {
            const float w = W1[d * UN + u];          // coalesced, L2/L1 resident
            a0 = fmaf(uS.encS[q * 2 + 0][d], w, a0);
            a1 = fmaf(uS.encS[q * 2 + 1][d], w, a1);
        }
        eS[q * 2 + 0][u] = a0;
        eS[q * 2 + 1][u] = a1;
    }
    __syncthreads();   // encS now dead

    const int warp = tid >> 5;
    const int lane = tid & 31;
    const int tt   = warp >> 1;                      // 0..7
    const int uh   = warp & 1;                       // u-half: rows uh*64..+63

    // ---- Phase A: barrier-free partial scores over full K, private u rows ---
    float s[8];
    #pragma unroll
    for (int j = 0; j < 8; j++) s[j] = 0.f;

    {
        // lane owns k = 4*lane + c (c=0..3) and k = 128 + 4*lane + c
        const float* kkp = g_kkT + (size_t)b * UN * Kp
                         + (size_t)(uh * 64) * Kp + lane * 4;
        const float* ep = &eS[tt][uh * 64];
        const float* vp = &Vs[uh * 64];
        #pragma unroll 4
        for (int u = 0; u < 64; u++) {
            const float e = ep[u];                   // smem broadcast
            const float v = vp[u];                   // smem broadcast
            const float4 r0 = *(const float4*)(kkp + (size_t)u * Kp);
            const float4 r1 = *(const float4*)(kkp + (size_t)u * Kp + 128);
            float th;
            asm("tanh.approx.f32 %0, %1;" : "=f"(th) : "f"(e + r0.x)); s[0] = fmaf(th, v, s[0]);
            asm("tanh.approx.f32 %0, %1;" : "=f"(th) : "f"(e + r0.y)); s[1] = fmaf(th, v, s[1]);
            asm("tanh.approx.f32 %0, %1;" : "=f"(th) : "f"(e + r0.z)); s[2] = fmaf(th, v, s[2]);
            asm("tanh.approx.f32 %0, %1;" : "=f"(th) : "f"(e + r0.w)); s[3] = fmaf(th, v, s[3]);
            asm("tanh.approx.f32 %0, %1;" : "=f"(th) : "f"(e + r1.x)); s[4] = fmaf(th, v, s[4]);
            asm("tanh.approx.f32 %0, %1;" : "=f"(th) : "f"(e + r1.y)); s[5] = fmaf(th, v, s[5]);
            asm("tanh.approx.f32 %0, %1;" : "=f"(th) : "f"(e + r1.z)); s[6] = fmaf(th, v, s[6]);
            asm("tanh.approx.f32 %0, %1;" : "=f"(th) : "f"(e + r1.w)); s[7] = fmaf(th, v, s[7]);
        }
    }
    // Store partials: k = 4*lane + c and 128 + 4*lane + c (two STS.128)
    *(float4*)&sP[uh][tt][lane * 4]       = make_float4(s[0], s[1], s[2], s[3]);
    *(float4*)&sP[uh][tt][128 + lane * 4] = make_float4(s[4], s[5], s[6], s[7]);
    __syncthreads();

    // ---- Combine partials + softmax. Warp (tt,uh) owns k-half uh:
    //      k = uh*128 + lane + 32c  (conflict-free smem pattern) ----
    float v4[4];
    {
        const int kb = uh * 128 + lane;
        #pragma unroll
        for (int c = 0; c < 4; c++)
            v4[c] = sP[0][tt][kb + 32 * c] + sP[1][tt][kb + 32 * c];
    }
    float mx = fmaxf(fmaxf(v4[0], v4[1]), fmaxf(v4[2], v4[3]));
    #pragma unroll
    for (int o = 16; o > 0; o >>= 1) mx = fmaxf(mx, __shfl_xor_sync(0xffffffffu, mx, o));
    if (lane == 0) redMax[warp] = mx;
    __syncthreads();
    mx = fmaxf(redMax[warp], redMax[warp ^ 1]);

    float sum = 0.f;
    #pragma unroll
    for (int c = 0; c < 4; c++) { v4[c] = __expf(v4[c] - mx); sum += v4[c]; }
    #pragma unroll
    for (int o = 16; o > 0; o >>= 1) sum += __shfl_xor_sync(0xffffffffu, sum, o);
    if (lane == 0) redSum[warp] = sum;
    __syncthreads();
    const float inv = 1.0f / (redSum[warp] + redSum[warp ^ 1]);
    {
        const int kb = uh * 128 + lane;
        #pragma unroll
        for (int c = 0; c < 4; c++)
            uS.wT[tt][kb + 32 * c] = v4[c] * inv;    // conflict-free STS
    }
    __syncthreads();

    // ---- Phase C: context. half g owns timesteps g*4..g*4+3, full K ----
    const int d = tid & 255;                         // 0..255 == DKp
    const int g = tid >> 8;                          // 0..1
    float acc[4];
    #pragma unroll
    for (int r = 0; r < 4; r++) acc[r] = 0.f;

    const float* knb = kn + (size_t)b * Kp * DKp + d;
    #pragma unroll 4
    for (int k = 0; k < Kp; k++) {
        const float kv = knb[(size_t)k * DKp];       // coalesced, L1/L2 resident
        acc[0] = fmaf(uS.wT[g * 4 + 0][k], kv, acc[0]);  // smem broadcasts
        acc[1] = fmaf(uS.wT[g * 4 + 1][k], kv, acc[1]);
        acc[2] = fmaf(uS.wT[g * 4 + 2][k], kv, acc[2]);
        acc[3] = fmaf(uS.wT[g * 4 + 3][k], kv, acc[3]);
    }
    #pragma unroll
    for (int r = 0; r < 4; r++)
        out[((size_t)(b * Tp + t0 + g * 4 + r)) * DKp + d] = acc[r];
}

// ---------------------------------------------------------------------------
// Harness entry point
// ---------------------------------------------------------------------------
extern "C" void kernel_launch(void* const* d_in, const int* in_sizes, int n_in,
                              void* d_out, int out_size)
{
    const float* kn  = (const float*)d_in[0];  // knowledge_onehot [B,K,D_K]
    const float* enc = (const float*)d_in[1];  // encoder_outputs  [B,T,D_ENC]
    const float* W1  = (const float*)d_in[2];  // [D_ENC,U]
    const float* b1  = (const float*)d_in[3];  // [U]
    const float* W2  = (const float*)d_in[4];  // [D_K,U]
    const float* b2  = (const float*)d_in[5];  // [U]
    const float* V   = (const float*)d_in[6];  // [U,1]
    // d_in[7] = bV: constant shift on scores, softmax-invariant -> ignored.
    float* out = (float*)d_out;                // context [B,T,D_K] fp32

    kk_pre_kernel<<<Bp * (Kp / 8), 256>>>(kn, W2, b2);
    attn_main_kernel<<<Bp * (Tp / TT), NTHR>>>(kn, enc, W1, b1, V, out);
}

// round 7
// speedup vs baseline: 1.2705x; 1.2119x over previous
#include <cuda_runtime.h>
#include <cstdint>

// Problem constants (fixed by the reference)
#define Bp    4
#define Tp    512
#define Kp    256
#define DENC  256
#define DKp   256
#define UN    128
#define TT    8     // timesteps per block
#define NTHR  512   // 16 warps: warp = (tt, u-half)

// Scratch
__device__ float g_kkT[Bp * UN * Kp];          // 512 KB: kkT[b][u][k]
__device__ float g_e[Bp * Tp * UN];            // 1 MB:  e[b*T+t][u]

// ---------------------------------------------------------------------------
// Prep kernel, grid = 384 blocks, 256 threads:
//   blocks [0,256):  e[row][u] = enc_row @ W1 + b1     (8 rows per block)
//   blocks [256,384): kkT[b][u][k] = (kn[b] @ W2 + b2)^T (8 k per block)
// ---------------------------------------------------------------------------
__global__ void __launch_bounds__(256) prep_kernel(
    const float* __restrict__ kn,
    const float* __restrict__ enc,
    const float* __restrict__ W1,
    const float* __restrict__ b1,
    const float* __restrict__ W2,
    const float* __restrict__ b2)
{
    __shared__ float rowS[8][256];           // 8 KB
    const int tid = threadIdx.x;

    if (blockIdx.x < 256) {
        // ---- e-projection: rows r0..r0+7 of flat [2048][256] encoder ----
        const int r0 = blockIdx.x * 8;
        {
            const float4* src = (const float4*)(enc + (size_t)r0 * DENC);
            float4* dst = (float4*)&rowS[0][0];
            dst[tid] = src[tid];
            dst[tid + 256] = src[tid + 256];
        }
        __syncthreads();

        const int u    = tid & 127;
        const int half = tid >> 7;           // rows half*4 .. half*4+3
        const float bb = b1[u];
        float a0 = bb, a1 = bb, a2 = bb, a3 = bb;
        #pragma unroll 8
        for (int d = 0; d < DENC; d++) {
            const float w = W1[d * UN + u];  // coalesced
            a0 = fmaf(rowS[half * 4 + 0][d], w, a0);
            a1 = fmaf(rowS[half * 4 + 1][d], w, a1);
            a2 = fmaf(rowS[half * 4 + 2][d], w, a2);
            a3 = fmaf(rowS[half * 4 + 3][d], w, a3);
        }
        float* eb = g_e + (size_t)r0 * UN + u;
        eb[(half * 4 + 0) * UN] = a0;
        eb[(half * 4 + 1) * UN] = a1;
        eb[(half * 4 + 2) * UN] = a2;
        eb[(half * 4 + 3) * UN] = a3;
    } else {
        // ---- kkT: b = idx>>5, k0 = (idx&31)*8 ----
        const int idx = blockIdx.x - 256;
        const int b   = idx >> 5;
        const int k0  = (idx & 31) * 8;
        {
            const float4* src = (const float4*)(kn + (size_t)(b * Kp + k0) * DKp);
            float4* dst = (float4*)&rowS[0][0];
            dst[tid] = src[tid];
            dst[tid + 256] = src[tid + 256];
        }
        __syncthreads();

        const int u    = tid & 127;
        const int half = tid >> 7;
        const float bb = b2[u];
        float a0 = bb, a1 = bb, a2 = bb, a3 = bb;
        #pragma unroll 8
        for (int d = 0; d < DKp; d++) {
            const float w = W2[d * UN + u];  // coalesced
            a0 = fmaf(rowS[half * 4 + 0][d], w, a0);
            a1 = fmaf(rowS[half * 4 + 1][d], w, a1);
            a2 = fmaf(rowS[half * 4 + 2][d], w, a2);
            a3 = fmaf(rowS[half * 4 + 3][d], w, a3);
        }
        float4* dst = (float4*)(g_kkT + (size_t)b * UN * Kp + (size_t)u * Kp + k0 + half * 4);
        *dst = make_float4(a0, a1, a2, a3);
    }
}

// ---------------------------------------------------------------------------
// Main kernel, 512 threads (16 warps), grid = B*(T/TT) = 256:
//   phase A: barrier-free partial scores (warp = (tt, u-half), private rows)
//   softmax: pair combine, weights stored k-major wT[K][8]
//   phase C: context GEMV with one broadcast LDS.128 per k-iter
// ---------------------------------------------------------------------------
__global__ void __launch_bounds__(NTHR, 2) attn_main_kernel(
    const float* __restrict__ kn,
    const float* __restrict__ V,
    float* __restrict__ out)
{
    __shared__ float eS[TT][UN];                    // 4 KB
    __shared__ float Vs[UN];                        // 0.5 KB
    __shared__ __align__(16) float sP[2][TT][Kp];   // 16 KB partial scores
    __shared__ __align__(16) float wT[Kp][TT];      // 8 KB, k-major weights
    __shared__ float redMax[16], redSum[16];

    const int tid = threadIdx.x;
    const int b   = blockIdx.x >> 6;                // 0..3
    const int t0  = (blockIdx.x & 63) * TT;         // 0..504

    // Stage e-tile (8x128 = 256 float4) + V
    if (tid < 256)
        ((float4*)&eS[0][0])[tid] =
            ((const float4*)(g_e + (size_t)(b * Tp + t0) * UN))[tid];
    else if (tid < 256 + UN)
        Vs[tid - 256] = V[tid - 256];
    __syncthreads();

    const int warp = tid >> 5;
    const int lane = tid & 31;
    const int tt   = warp >> 1;                     // 0..7
    const int uh   = warp & 1;                      // u-half: rows uh*64..+63

    // ---- Phase A: barrier-free partial scores over full K, private u rows --
    float s[8];
    #pragma unroll
    for (int j = 0; j < 8; j++) s[j] = 0.f;
    {
        const float* kkp = g_kkT + (size_t)b * UN * Kp
                         + (size_t)(uh * 64) * Kp + lane * 4;
        const float* ep = &eS[tt][uh * 64];
        const float* vp = &Vs[uh * 64];
        #pragma unroll 4
        for (int u = 0; u < 64; u++) {
            const float e = ep[u];
            const float v = vp[u];
            const float4 r0 = *(const float4*)(kkp + (size_t)u * Kp);
            const float4 r1 = *(const float4*)(kkp + (size_t)u * Kp + 128);
            float th;
            asm("tanh.approx.f32 %0, %1;" : "=f"(th) : "f"(e + r0.x)); s[0] = fmaf(th, v, s[0]);
            asm("tanh.approx.f32 %0, %1;" : "=f"(th) : "f"(e + r0.y)); s[1] = fmaf(th, v, s[1]);
            asm("tanh.approx.f32 %0, %1;" : "=f"(th) : "f"(e + r0.z)); s[2] = fmaf(th, v, s[2]);
            asm("tanh.approx.f32 %0, %1;" : "=f"(th) : "f"(e + r0.w)); s[3] = fmaf(th, v, s[3]);
            asm("tanh.approx.f32 %0, %1;" : "=f"(th) : "f"(e + r1.x)); s[4] = fmaf(th, v, s[4]);
            asm("tanh.approx.f32 %0, %1;" : "=f"(th) : "f"(e + r1.y)); s[5] = fmaf(th, v, s[5]);
            asm("tanh.approx.f32 %0, %1;" : "=f"(th) : "f"(e + r1.z)); s[6] = fmaf(th, v, s[6]);
            asm("tanh.approx.f32 %0, %1;" : "=f"(th) : "f"(e + r1.w)); s[7] = fmaf(th, v, s[7]);
        }
    }
    *(float4*)&sP[uh][tt][lane * 4]       = make_float4(s[0], s[1], s[2], s[3]);
    *(float4*)&sP[uh][tt][128 + lane * 4] = make_float4(s[4], s[5], s[6], s[7]);
    __syncthreads();

    // ---- Combine + softmax. Warp (tt,uh) owns k = uh*128 + lane + 32c ----
    float v4[4];
    {
        const int kb = uh * 128 + lane;
        #pragma unroll
        for (int c = 0; c < 4; c++)
            v4[c] = sP[0][tt][kb + 32 * c] + sP[1][tt][kb + 32 * c];
    }
    float mx = fmaxf(fmaxf(v4[0], v4[1]), fmaxf(v4[2], v4[3]));
    #pragma unroll
    for (int o = 16; o > 0; o >>= 1) mx = fmaxf(mx, __shfl_xor_sync(0xffffffffu, mx, o));
    if (lane == 0) redMax[warp] = mx;
    __syncthreads();
    mx = fmaxf(redMax[warp], redMax[warp ^ 1]);

    float sum = 0.f;
    #pragma unroll
    for (int c = 0; c < 4; c++) { v4[c] = __expf(v4[c] - mx); sum += v4[c]; }
    #pragma unroll
    for (int o = 16; o > 0; o >>= 1) sum += __shfl_xor_sync(0xffffffffu, sum, o);
    if (lane == 0) redSum[warp] = sum;
    __syncthreads();
    const float inv = 1.0f / (redSum[warp] + redSum[warp ^ 1]);
    {
        const int kb = uh * 128 + lane;
        #pragma unroll
        for (int c = 0; c < 4; c++)
            wT[kb + 32 * c][tt] = v4[c] * inv;      // k-major for phase C
    }
    __syncthreads();

    // ---- Phase C: context. half g owns timesteps g*4..g*4+3, full K ----
    const int d = tid & 255;                        // 0..255 == DKp
    const int g = tid >> 8;                         // 0..1
    float acc[4];
    #pragma unroll
    for (int r = 0; r < 4; r++) acc[r] = 0.f;

    const float* knb = kn + (size_t)b * Kp * DKp + d;
    #pragma unroll 4
    for (int k = 0; k < Kp; k++) {
        const float kv = knb[(size_t)k * DKp];      // coalesced LDG, L1/L2 hot
        const float4 w = *(const float4*)&wT[k][g * 4];  // broadcast LDS.128
        acc[0] = fmaf(w.x, kv, acc[0]);
        acc[1] = fmaf(w.y, kv, acc[1]);
        acc[2] = fmaf(w.z, kv, acc[2]);
        acc[3] = fmaf(w.w, kv, acc[3]);
    }
    #pragma unroll
    for (int r = 0; r < 4; r++)
        out[((size_t)(b * Tp + t0 + g * 4 + r)) * DKp + d] = acc[r];
}

// ---------------------------------------------------------------------------
// Harness entry point
// ---------------------------------------------------------------------------
extern "C" void kernel_launch(void* const* d_in, const int* in_sizes, int n_in,
                              void* d_out, int out_size)
{
    const float* kn  = (const float*)d_in[0];  // knowledge_onehot [B,K,D_K]
    const float* enc = (const float*)d_in[1];  // encoder_outputs  [B,T,D_ENC]
    const float* W1  = (const float*)d_in[2];  // [D_ENC,U]
    const float* b1  = (const float*)d_in[3];  // [U]
    const float* W2  = (const float*)d_in[4];  // [D_K,U]
    const float* b2  = (const float*)d_in[5];  // [U]
    const float* V   = (const float*)d_in[6];  // [U,1]
    // d_in[7] = bV: constant shift on scores, softmax-invariant -> ignored.
    float* out = (float*)d_out;                // context [B,T,D_K] fp32

    prep_kernel<<<384, 256>>>(kn, enc, W1, b1, W2, b2);
    attn_main_kernel<<<Bp * (Tp / TT), NTHR>>>(kn, V, out);
}

// round 8
// speedup vs baseline: 1.3697x; 1.0780x over previous
#include <cuda_runtime.h>
#include <cstdint>

// Problem constants (fixed by the reference)
#define Bp    4
#define Tp    512
#define Kp    256
#define DENC  256
#define DKp   256
#define UN    128
#define TT    4     // timesteps per block
#define NTHR  256   // 8 warps: warp = (tt, u-half)

// Scratch
__device__ float g_kkT[Bp * UN * Kp];          // 512 KB: kkT[b][u][k]
__device__ float g_e[Bp * Tp * UN];            // 1 MB:  e[b*T+t][u]

// ---------------------------------------------------------------------------
// Prep kernel, grid = 384 blocks, 256 threads:
//   blocks [0,256):  e[row][u] = enc_row @ W1 + b1     (8 rows per block)
//   blocks [256,384): kkT[b][u][k] = (kn[b] @ W2 + b2)^T (8 k per block)
// ---------------------------------------------------------------------------
__global__ void __launch_bounds__(256) prep_kernel(
    const float* __restrict__ kn,
    const float* __restrict__ enc,
    const float* __restrict__ W1,
    const float* __restrict__ b1,
    const float* __restrict__ W2,
    const float* __restrict__ b2)
{
    __shared__ float rowS[8][256];           // 8 KB
    const int tid = threadIdx.x;

    if (blockIdx.x < 256) {
        // ---- e-projection: rows r0..r0+7 of flat [2048][256] encoder ----
        const int r0 = blockIdx.x * 8;
        {
            const float4* src = (const float4*)(enc + (size_t)r0 * DENC);
            float4* dst = (float4*)&rowS[0][0];
            dst[tid] = src[tid];
            dst[tid + 256] = src[tid + 256];
        }
        __syncthreads();

        const int u    = tid & 127;
        const int half = tid >> 7;           // rows half*4 .. half*4+3
        const float bb = b1[u];
        float a0 = bb, a1 = bb, a2 = bb, a3 = bb;
        #pragma unroll 8
        for (int d = 0; d < DENC; d++) {
            const float w = W1[d * UN + u];  // coalesced
            a0 = fmaf(rowS[half * 4 + 0][d], w, a0);
            a1 = fmaf(rowS[half * 4 + 1][d], w, a1);
            a2 = fmaf(rowS[half * 4 + 2][d], w, a2);
            a3 = fmaf(rowS[half * 4 + 3][d], w, a3);
        }
        float* eb = g_e + (size_t)r0 * UN + u;
        eb[(half * 4 + 0) * UN] = a0;
        eb[(half * 4 + 1) * UN] = a1;
        eb[(half * 4 + 2) * UN] = a2;
        eb[(half * 4 + 3) * UN] = a3;
    } else {
        // ---- kkT: b = idx>>5, k0 = (idx&31)*8 ----
        const int idx = blockIdx.x - 256;
        const int b   = idx >> 5;
        const int k0  = (idx & 31) * 8;
        {
            const float4* src = (const float4*)(kn + (size_t)(b * Kp + k0) * DKp);
            float4* dst = (float4*)&rowS[0][0];
            dst[tid] = src[tid];
            dst[tid + 256] = src[tid + 256];
        }
        __syncthreads();

        const int u    = tid & 127;
        const int half = tid >> 7;
        const float bb = b2[u];
        float a0 = bb, a1 = bb, a2 = bb, a3 = bb;
        #pragma unroll 8
        for (int d = 0; d < DKp; d++) {
            const float w = W2[d * UN + u];  // coalesced
            a0 = fmaf(rowS[half * 4 + 0][d], w, a0);
            a1 = fmaf(rowS[half * 4 + 1][d], w, a1);
            a2 = fmaf(rowS[half * 4 + 2][d], w, a2);
            a3 = fmaf(rowS[half * 4 + 3][d], w, a3);
        }
        float4* dst = (float4*)(g_kkT + (size_t)b * UN * Kp + (size_t)u * Kp + k0 + half * 4);
        *dst = make_float4(a0, a1, a2, a3);
    }
}

// ---------------------------------------------------------------------------
// Main kernel, 256 threads (8 warps), grid = B*(T/TT) = 512:
//   4 independent blocks per SM -> phase diversity (MUFU-phase of one block
//   overlaps FMA/LDG-phase of another) and narrow barrier convoys.
//   phase A: barrier-free partial scores (warp = (tt, u-half), private rows)
//   softmax: pair combine, weights stored k-major wT[K][4]
//   phase C: context GEMV, unroll 8 for MLP, broadcast LDS.128 weights
// ---------------------------------------------------------------------------
__global__ void __launch_bounds__(NTHR, 4) attn_main_kernel(
    const float* __restrict__ kn,
    const float* __restrict__ V,
    float* __restrict__ out)
{
    __shared__ float eS[TT][UN];                    // 2 KB
    __shared__ float Vs[UN];                        // 0.5 KB
    __shared__ __align__(16) float sP[2][TT][Kp];   // 8 KB partial scores
    __shared__ __align__(16) float wT[Kp][TT];      // 4 KB, k-major weights
    __shared__ float redMax[8], redSum[8];

    const int tid = threadIdx.x;
    const int b   = blockIdx.x >> 7;                // 0..3
    const int t0  = (blockIdx.x & 127) * TT;        // 0..508

    // Stage e-tile (4x128 = 128 float4) + V (128 floats)
    if (tid < 128)
        ((float4*)&eS[0][0])[tid] =
            ((const float4*)(g_e + (size_t)(b * Tp + t0) * UN))[tid];
    else
        Vs[tid - 128] = V[tid - 128];
    __syncthreads();

    const int warp = tid >> 5;
    const int lane = tid & 31;
    const int tt   = warp >> 1;                     // 0..3
    const int uh   = warp & 1;                      // u-half: rows uh*64..+63

    // ---- Phase A: barrier-free partial scores over full K, private u rows --
    float s[8];
    #pragma unroll
    for (int j = 0; j < 8; j++) s[j] = 0.f;
    {
        const float* kkp = g_kkT + (size_t)b * UN * Kp
                         + (size_t)(uh * 64) * Kp + lane * 4;
        const float* ep = &eS[tt][uh * 64];
        const float* vp = &Vs[uh * 64];
        #pragma unroll 4
        for (int u = 0; u < 64; u++) {
            const float e = ep[u];
            const float v = vp[u];
            const float4 r0 = *(const float4*)(kkp + (size_t)u * Kp);
            const float4 r1 = *(const float4*)(kkp + (size_t)u * Kp + 128);
            float th;
            asm("tanh.approx.f32 %0, %1;" : "=f"(th) : "f"(e + r0.x)); s[0] = fmaf(th, v, s[0]);
            asm("tanh.approx.f32 %0, %1;" : "=f"(th) : "f"(e + r0.y)); s[1] = fmaf(th, v, s[1]);
            asm("tanh.approx.f32 %0, %1;" : "=f"(th) : "f"(e + r0.z)); s[2] = fmaf(th, v, s[2]);
            asm("tanh.approx.f32 %0, %1;" : "=f"(th) : "f"(e + r0.w)); s[3] = fmaf(th, v, s[3]);
            asm("tanh.approx.f32 %0, %1;" : "=f"(th) : "f"(e + r1.x)); s[4] = fmaf(th, v, s[4]);
            asm("tanh.approx.f32 %0, %1;" : "=f"(th) : "f"(e + r1.y)); s[5] = fmaf(th, v, s[5]);
            asm("tanh.approx.f32 %0, %1;" : "=f"(th) : "f"(e + r1.z)); s[6] = fmaf(th, v, s[6]);
            asm("tanh.approx.f32 %0, %1;" : "=f"(th) : "f"(e + r1.w)); s[7] = fmaf(th, v, s[7]);
        }
    }
    *(float4*)&sP[uh][tt][lane * 4]       = make_float4(s[0], s[1], s[2], s[3]);
    *(float4*)&sP[uh][tt][128 + lane * 4] = make_float4(s[4], s[5], s[6], s[7]);
    __syncthreads();

    // ---- Combine + softmax. Warp (tt,uh) owns k = uh*128 + lane + 32c ----
    float v4[4];
    {
        const int kb = uh * 128 + lane;
        #pragma unroll
        for (int c = 0; c < 4; c++)
            v4[c] = sP[0][tt][kb + 32 * c] + sP[1][tt][kb + 32 * c];
    }
    float mx = fmaxf(fmaxf(v4[0], v4[1]), fmaxf(v4[2], v4[3]));
    #pragma unroll
    for (int o = 16; o > 0; o >>= 1) mx = fmaxf(mx, __shfl_xor_sync(0xffffffffu, mx, o));
    if (lane == 0) redMax[warp] = mx;
    __syncthreads();
    mx = fmaxf(redMax[warp], redMax[warp ^ 1]);

    float sum = 0.f;
    #pragma unroll
    for (int c = 0; c < 4; c++) { v4[c] = __expf(v4[c] - mx); sum += v4[c]; }
    #pragma unroll
    for (int o = 16; o > 0; o >>= 1) sum += __shfl_xor_sync(0xffffffffu, sum, o);
    if (lane == 0) redSum[warp] = sum;
    __syncthreads();
    const float inv = 1.0f / (redSum[warp] + redSum[warp ^ 1]);
    {
        const int kb = uh * 128 + lane;
        #pragma unroll
        for (int c = 0; c < 4; c++)
            wT[kb + 32 * c][tt] = v4[c] * inv;      // k-major for phase C
    }
    __syncthreads();

    // ---- Phase C: context. Thread owns d = tid, all 4 timesteps, full K ----
    const int d = tid;                              // 0..255 == DKp
    float acc[TT];
    #pragma unroll
    for (int r = 0; r < TT; r++) acc[r] = 0.f;

    const float* knb = kn + (size_t)b * Kp * DKp + d;
    #pragma unroll 8
    for (int k = 0; k < Kp; k++) {
        const float kv = knb[(size_t)k * DKp];      // coalesced LDG, L1/L2 hot
        const float4 w = *(const float4*)&wT[k][0]; // broadcast LDS.128
        acc[0] = fmaf(w.x, kv, acc[0]);
        acc[1] = fmaf(w.y, kv, acc[1]);
        acc[2] = fmaf(w.z, kv, acc[2]);
        acc[3] = fmaf(w.w, kv, acc[3]);
    }
    #pragma unroll
    for (int r = 0; r < TT; r++)
        out[((size_t)(b * Tp + t0 + r)) * DKp + d] = acc[r];
}

// ---------------------------------------------------------------------------
// Harness entry point
// ---------------------------------------------------------------------------
extern "C" void kernel_launch(void* const* d_in, const int* in_sizes, int n_in,
                              void* d_out, int out_size)
{
    const float* kn  = (const float*)d_in[0];  // knowledge_onehot [B,K,D_K]
    const float* enc = (const float*)d_in[1];  // encoder_outputs  [B,T,D_ENC]
    const float* W1  = (const float*)d_in[2];  // [D_ENC,U]
    const float* b1  = (const float*)d_in[3];  // [U]
    const float* W2  = (const float*)d_in[4];  // [D_K,U]
    const float* b2  = (const float*)d_in[5];  // [U]
    const float* V   = (const float*)d_in[6];  // [U,1]
    // d_in[7] = bV: constant shift on scores, softmax-invariant -> ignored.
    float* out = (float*)d_out;                // context [B,T,D_K] fp32

    prep_kernel<<<384, 256>>>(kn, enc, W1, b1, W2, b2);
    attn_main_kernel<<<Bp * (Tp / TT), NTHR>>>(kn, V, out);
}